// round 11
// baseline (speedup 1.0000x reference)
#include <cuda_runtime.h>
#include <math.h>
#include <string.h>

// GaussianBlurDM, round 10: fused kernel, high occupancy, no staging pipeline.
//
// out[b] = reflect-conv(reflect-conv(x[b], K_t, axis=H), K_t, axis=W),
// K_t = t-fold self-convolution of the 11-tap Gaussian (exact DCT-I identity),
// truncated at tail mass 1.5e-4, taps padded to 8 (padding = true tail wts).
//
// One CTA = 16x256 output tile, 256 threads, ~18KB smem, 4 CTAs/SM:
//   V phase: 8-slot __ldg register ring straight from global; refill->use
//            distance 64 issue-slots/warp x 8 warps/SMSP covers L2 latency.
//            Result written transposed to smem sv[col][row] (float2 stores --
//            both column parities 8B-aligned with SVSTRIDE=18).
//   H phase: same 8-slot ring fed from LDS over sv columns (interior groups
//            reflect-free), coalesced natural-layout float4 stores.

#define BATCH 64
#define CHAN 3
#define IMG 256
#define NT 19
#define NSLOT (NT + 1)     // slot NT = identity (t <= 0 safety)
#define NDPMAX 64
#define SVSTRIDE 18        // floats per sv column (16 rows + 2 pad)
#define SV_U64 (SVSTRIDE / 2)
#define SMEM_BYTES (IMG * SVSTRIDE * 4)   // 18432 B

typedef unsigned long long u64;

struct BlurParams {
    u64 K[NSLOT][NDPMAX];   // weight duplicated into both f32 lanes
    int rl[NSLOT];          // left radius (tap 0 offset = -rl)
    int ndp[NSLOT];         // tap count, multiple of 8, <= NDPMAX
};

__device__ __forceinline__ int reflect256(int v) {
    v = abs(v);
    return (v > 255) ? (510 - v) : v;
}

__device__ __forceinline__ u64 ffma2(u64 a, u64 b, u64 c) {
    u64 d;
    asm("fma.rn.f32x2 %0, %1, %2, %3;" : "=l"(d) : "l"(a), "l"(b), "l"(c));
    return d;
}

__device__ __forceinline__ void unpack2(u64 v, float& x, float& y) {
    asm("mov.b64 {%0, %1}, %2;" : "=f"(x), "=f"(y) : "l"(v));
}

__global__ void __launch_bounds__(256, 4) blur_fused(
    const float* __restrict__ src, float* __restrict__ dst,
    const int* __restrict__ t, const __grid_constant__ BlurParams P)
{
    __shared__ float sv[IMG * SVSTRIDE];

    const int tid = threadIdx.x;
    const int m0 = blockIdx.x << 4;                 // tile's first output row
    const int bc = blockIdx.z * CHAN + blockIdx.y;
    const float* img = src + ((long)bc << 16);
    float* gout = dst + ((long)bc << 16);

    const int tb = t[blockIdx.z];
    const int ti = (tb >= 1) ? ((tb > NT) ? (NT - 1) : (tb - 1)) : NT;
    const u64* __restrict__ Kw = P.K[ti];           // constant bank
    const int rl = P.rl[ti];
    const int ndp = P.ndp[ti];

    u64 acc[8], ring[8];

    // ================= V phase: global __ldg ring over rows ==================
    {
        const int cp_ = tid & 127;                  // column pair
        const int half = tid >> 7;                  // 8-row half
        const u64* __restrict__ scol = (const u64*)img + cp_;  // row stride 128
        const int vb = m0 + (half << 3) - rl;       // input row of tap 0

        #pragma unroll
        for (int k = 0; k < 8; ++k) acc[k] = 0ull;
        #pragma unroll
        for (int m = 0; m < 8; ++m)
            ring[m] = __ldg(scol + (reflect256(vb + m) << 7));

        #pragma unroll 1
        for (int jj = 0; jj < ndp; jj += 8) {
            #pragma unroll
            for (int u = 0; u < 8; ++u) {
                const int j = jj + u;
                u64 w = Kw[j];
                #pragma unroll
                for (int k = 0; k < 8; ++k)
                    acc[k] = ffma2(ring[(j + k) & 7], w, acc[k]);
                ring[j & 7] = __ldg(scol + (reflect256(vb + j + 8) << 7));
            }
        }

        // Store transposed to sv (float2: both column parities 8B-aligned).
        const int c0 = cp_ << 1;
        const int mr = half << 3;
        float lo[8], hi[8];
        #pragma unroll
        for (int k = 0; k < 8; ++k) unpack2(acc[k], lo[k], hi[k]);
        float2* p0 = (float2*)(sv + c0 * SVSTRIDE + mr);
        float2* p1 = (float2*)(sv + (c0 + 1) * SVSTRIDE + mr);
        #pragma unroll
        for (int q = 0; q < 4; ++q) {
            p0[q] = make_float2(lo[2 * q], lo[2 * q + 1]);
            p1[q] = make_float2(hi[2 * q], hi[2 * q + 1]);
        }
    }

    __syncthreads();

    // ================= H phase: LDS ring over sv columns =====================
    {
        const int rp = tid & 7;                     // row pair (rows 2rp,2rp+1)
        const int cg = tid >> 3;                    // 8-col group 0..31
        const u64* __restrict__ sb = (const u64*)sv + rp;
        const int qb = (cg << 3) - rl;              // first input col

        #pragma unroll
        for (int k = 0; k < 8; ++k) acc[k] = 0ull;

        if (qb >= 0 && qb + ndp + 7 <= 255) {
            // interior fast path: linear columns
            const u64* pH = sb + qb * SV_U64;
            #pragma unroll
            for (int m = 0; m < 8; ++m) ring[m] = pH[m * SV_U64];
            #pragma unroll 1
            for (int jj = 0; jj < ndp; jj += 8) {
                #pragma unroll
                for (int u = 0; u < 8; ++u) {
                    const int j = jj + u;
                    u64 w = Kw[j];
                    #pragma unroll
                    for (int k = 0; k < 8; ++k)
                        acc[k] = ffma2(ring[(j + k) & 7], w, acc[k]);
                    ring[j & 7] = pH[(j + 8) * SV_U64];
                }
            }
        } else {
            // boundary path: reflected columns
            #pragma unroll
            for (int m = 0; m < 8; ++m)
                ring[m] = sb[reflect256(qb + m) * SV_U64];
            #pragma unroll 1
            for (int jj = 0; jj < ndp; jj += 8) {
                #pragma unroll
                for (int u = 0; u < 8; ++u) {
                    const int j = jj + u;
                    u64 w = Kw[j];
                    #pragma unroll
                    for (int k = 0; k < 8; ++k)
                        acc[k] = ffma2(ring[(j + k) & 7], w, acc[k]);
                    ring[j & 7] = sb[reflect256(qb + j + 8) * SV_U64];
                }
            }
        }

        // Natural-layout store: rows m0+2rp(+1), cols cg*8..+7.
        float lo[8], hi[8];
        #pragma unroll
        for (int k = 0; k < 8; ++k) unpack2(acc[k], lo[k], hi[k]);
        float4* d0 = (float4*)(gout + (m0 + 2 * rp) * IMG + (cg << 3));
        float4* d1 = (float4*)(gout + (m0 + 2 * rp + 1) * IMG + (cg << 3));
        d0[0] = make_float4(lo[0], lo[1], lo[2], lo[3]);
        d0[1] = make_float4(lo[4], lo[5], lo[6], lo[7]);
        d1[0] = make_float4(hi[0], hi[1], hi[2], hi[3]);
        d1[1] = make_float4(hi[4], hi[5], hi[6], hi[7]);
    }
}

// ---------------------------------------------------------------------------
extern "C" void kernel_launch(void* const* d_in, const int* in_sizes, int n_in,
                              void* d_out, int out_size) {
    const float* x = (const float*)d_in[0];
    const int* t = (const int*)d_in[1];
    float* out = (float*)d_out;

    static BlurParams P;
    memset(&P, 0, sizeof(P));
    {
        // Base kernel, f32-rounded exactly like the reference's _k1d.
        double pdf[11], sum = 0.0;
        for (int i = 0; i < 11; ++i) {
            double xi = -5.0 + (double)i;
            pdf[i] = exp(-0.5 * (xi / 2.0) * (xi / 2.0));
            sum += pdf[i];
        }
        double base[11];
        for (int i = 0; i < 11; ++i)
            base[i] = (double)((float)(pdf[i] / sum));

        double f[220];
        for (int i = 0; i < 220; ++i) f[i] = 0.0;
        for (int i = 0; i < 11; ++i) f[i] = base[i];
        int hw = 5;

        const double TAIL = 1.5e-4;
        for (int tt = 1; tt <= NT; ++tt) {
            double acc = 0.0;
            int r = 0;
            for (int a = hw; a >= 1; --a) {
                acc += f[hw + a];
                if (2.0 * acc > TAIL) { r = a; break; }
            }
            int ndp = (2 * r + 1 + 7) & ~7;          // pad taps to 8
            if (ndp > NDPMAX) ndp = NDPMAX;
            int rl = ndp / 2;                        // window: -rl .. ndp-1-rl
            P.rl[tt - 1] = rl;
            P.ndp[tt - 1] = ndp;
            for (int jj = 0; jj < ndp; ++jj) {
                int off = jj - rl;                   // true tail wts in padding
                float w = (off >= -hw && off <= hw) ? (float)f[hw + off] : 0.0f;
                float2 w2 = make_float2(w, w);
                memcpy(&P.K[tt - 1][jj], &w2, 8);
            }
            if (tt < NT) {   // f = f (*) base
                int L = 2 * hw + 1;
                double g[220];
                for (int i = 0; i < 220; ++i) g[i] = 0.0;
                for (int n = 0; n < L; ++n) {
                    double fn = f[n];
                    for (int k = 0; k < 11; ++k) g[n + k] += fn * base[k];
                }
                for (int i = 0; i < 220; ++i) f[i] = g[i];
                hw += 5;
            }
        }
        // Identity slot (t <= 0 safety): unit tap at offset 0 -> exact copy.
        P.rl[NT] = 4;
        P.ndp[NT] = 8;
        float2 one = make_float2(1.0f, 1.0f);
        memcpy(&P.K[NT][4], &one, 8);
    }

    dim3 block(256);
    dim3 grid(IMG / 16, CHAN, BATCH);   // 16 x 3 x 64 = 3072 CTAs
    blur_fused<<<grid, block>>>(x, out, t, P);
}

// round 12
// speedup vs baseline: 1.0606x; 1.0606x over previous
#include <cuda_runtime.h>
#include <math.h>
#include <string.h>

// GaussianBlurDM, round 11: evict address IMADs from the fma pipe.
//
// out[b] = reflect-conv(reflect-conv(x[b], K_t, axis=H), K_t, axis=W),
// K_t = t-fold self-convolution of the 11-tap Gaussian (exact DCT-I identity),
// truncated at tail mass 5e-4, taps padded to 8 (padding = true tail weights).
//
// One CTA = 16x256 output tile, 256 threads, 18KB smem, 4 CTAs/SM.
// Both phases: 8 packed accumulators (fma.rn.f32x2) + 8-slot register ring.
// INTERIOR CTAs/column-groups take a fast path with immediate-offset loads
// (no reflect, no IMAD in the loop) -- IMAD shares the fma pipe with FFMA2
// at rt=2 and was stealing ~half its throughput in rounds 7-10.

#define BATCH 64
#define CHAN 3
#define IMG 256
#define NT 19
#define NSLOT (NT + 1)     // slot NT = identity (t <= 0 safety)
#define NDPMAX 64
#define SVSTRIDE 18        // floats per sv column (16 rows + 2 pad)
#define SV_U64 (SVSTRIDE / 2)

typedef unsigned long long u64;

struct BlurParams {
    u64 K[NSLOT][NDPMAX];   // weight duplicated into both f32 lanes
    int rl[NSLOT];          // left radius (tap 0 offset = -rl)
    int ndp[NSLOT];         // tap count, multiple of 8, <= NDPMAX
};

__device__ __forceinline__ int reflect256(int v) {
    v = abs(v);
    return (v > 255) ? (510 - v) : v;
}

__device__ __forceinline__ u64 ffma2(u64 a, u64 b, u64 c) {
    u64 d;
    asm("fma.rn.f32x2 %0, %1, %2, %3;" : "=l"(d) : "l"(a), "l"(b), "l"(c));
    return d;
}

__device__ __forceinline__ void unpack2(u64 v, float& x, float& y) {
    asm("mov.b64 {%0, %1}, %2;" : "=f"(x), "=f"(y) : "l"(v));
}

__global__ void __launch_bounds__(256, 4) blur_fused(
    const float* __restrict__ src, float* __restrict__ dst,
    const int* __restrict__ t, const __grid_constant__ BlurParams P)
{
    __shared__ float sv[IMG * SVSTRIDE];

    const int tid = threadIdx.x;
    const int m0 = blockIdx.x << 4;                 // tile's first output row
    const int bc = blockIdx.z * CHAN + blockIdx.y;
    const float* img = src + ((long)bc << 16);
    float* gout = dst + ((long)bc << 16);

    const int tb = t[blockIdx.z];
    const int ti = (tb >= 1) ? ((tb > NT) ? (NT - 1) : (tb - 1)) : NT;
    const u64* __restrict__ Kw = P.K[ti];           // constant bank (uniform)
    const int rl = P.rl[ti];
    const int ndp = P.ndp[ti];

    u64 acc[8], ring[8];

    // ================= V phase: ring over rows, straight from global ========
    {
        const int cp_ = tid & 127;                  // column pair
        const int half = tid >> 7;                  // 8-row half
        const u64* __restrict__ scol = (const u64*)img + cp_;  // row stride 128
        const int vb = m0 + (half << 3) - rl;       // input row of tap 0

        #pragma unroll
        for (int k = 0; k < 8; ++k) acc[k] = 0ull;

        // CTA-uniform interior test: all rows read are vb .. vb+ndp+7 (half<=1)
        if (m0 - rl >= 0 && m0 + 8 - rl + ndp + 7 <= 255) {
            // ---- fast path: linear rows, immediate-offset LDG ----
            const u64* pV = scol + (vb << 7);
            #pragma unroll
            for (int m = 0; m < 8; ++m) ring[m] = __ldg(pV + (m << 7));
            #pragma unroll 1
            for (int jj = 0; jj < ndp; jj += 8) {
                const u64* pb = pV + ((jj + 8) << 7);   // one LEA per block
                #pragma unroll
                for (int u = 0; u < 8; ++u) {
                    u64 w = Kw[jj + u];
                    #pragma unroll
                    for (int k = 0; k < 8; ++k)
                        acc[k] = ffma2(ring[(u + k) & 7], w, acc[k]);
                    ring[u] = __ldg(pb + (u << 7));     // immediate offset
                }
            }
        } else {
            // ---- boundary path: reflected rows ----
            #pragma unroll
            for (int m = 0; m < 8; ++m)
                ring[m] = __ldg(scol + (reflect256(vb + m) << 7));
            #pragma unroll 1
            for (int jj = 0; jj < ndp; jj += 8) {
                #pragma unroll
                for (int u = 0; u < 8; ++u) {
                    u64 w = Kw[jj + u];
                    #pragma unroll
                    for (int k = 0; k < 8; ++k)
                        acc[k] = ffma2(ring[(u + k) & 7], w, acc[k]);
                    ring[u] = __ldg(scol + (reflect256(vb + jj + u + 8) << 7));
                }
            }
        }

        // Store transposed to sv (float2: both column parities 8B-aligned).
        const int c0 = cp_ << 1;
        const int mr = half << 3;
        float lo[8], hi[8];
        #pragma unroll
        for (int k = 0; k < 8; ++k) unpack2(acc[k], lo[k], hi[k]);
        float2* p0 = (float2*)(sv + c0 * SVSTRIDE + mr);
        float2* p1 = (float2*)(sv + (c0 + 1) * SVSTRIDE + mr);
        #pragma unroll
        for (int q = 0; q < 4; ++q) {
            p0[q] = make_float2(lo[2 * q], lo[2 * q + 1]);
            p1[q] = make_float2(hi[2 * q], hi[2 * q + 1]);
        }
    }

    __syncthreads();

    // ================= H phase: LDS ring over sv columns =====================
    {
        const int rp = tid & 7;                     // row pair (rows 2rp,2rp+1)
        const int cg = tid >> 3;                    // 8-col group 0..31
        const u64* __restrict__ sb = (const u64*)sv + rp;
        const int qb = (cg << 3) - rl;              // first input col

        #pragma unroll
        for (int k = 0; k < 8; ++k) acc[k] = 0ull;

        if (qb >= 0 && qb + ndp + 7 <= 255) {
            // interior fast path: linear columns, immediate offsets
            const u64* pH = sb + qb * SV_U64;
            #pragma unroll
            for (int m = 0; m < 8; ++m) ring[m] = pH[m * SV_U64];
            #pragma unroll 1
            for (int jj = 0; jj < ndp; jj += 8) {
                const u64* pb = pH + (jj + 8) * SV_U64;
                #pragma unroll
                for (int u = 0; u < 8; ++u) {
                    u64 w = Kw[jj + u];
                    #pragma unroll
                    for (int k = 0; k < 8; ++k)
                        acc[k] = ffma2(ring[(u + k) & 7], w, acc[k]);
                    ring[u] = pb[u * SV_U64];           // immediate offset
                }
            }
        } else {
            // boundary path: reflected columns
            #pragma unroll
            for (int m = 0; m < 8; ++m)
                ring[m] = sb[reflect256(qb + m) * SV_U64];
            #pragma unroll 1
            for (int jj = 0; jj < ndp; jj += 8) {
                #pragma unroll
                for (int u = 0; u < 8; ++u) {
                    u64 w = Kw[jj + u];
                    #pragma unroll
                    for (int k = 0; k < 8; ++k)
                        acc[k] = ffma2(ring[(u + k) & 7], w, acc[k]);
                    ring[u] = sb[reflect256(qb + jj + u + 8) * SV_U64];
                }
            }
        }

        // Natural-layout store: rows m0+2rp(+1), cols cg*8..+7.
        float lo[8], hi[8];
        #pragma unroll
        for (int k = 0; k < 8; ++k) unpack2(acc[k], lo[k], hi[k]);
        float4* d0 = (float4*)(gout + (m0 + 2 * rp) * IMG + (cg << 3));
        float4* d1 = (float4*)(gout + (m0 + 2 * rp + 1) * IMG + (cg << 3));
        d0[0] = make_float4(lo[0], lo[1], lo[2], lo[3]);
        d0[1] = make_float4(lo[4], lo[5], lo[6], lo[7]);
        d1[0] = make_float4(hi[0], hi[1], hi[2], hi[3]);
        d1[1] = make_float4(hi[4], hi[5], hi[6], hi[7]);
    }
}

// ---------------------------------------------------------------------------
extern "C" void kernel_launch(void* const* d_in, const int* in_sizes, int n_in,
                              void* d_out, int out_size) {
    const float* x = (const float*)d_in[0];
    const int* t = (const int*)d_in[1];
    float* out = (float*)d_out;

    static BlurParams P;
    memset(&P, 0, sizeof(P));
    {
        // Base kernel, f32-rounded exactly like the reference's _k1d.
        double pdf[11], sum = 0.0;
        for (int i = 0; i < 11; ++i) {
            double xi = -5.0 + (double)i;
            pdf[i] = exp(-0.5 * (xi / 2.0) * (xi / 2.0));
            sum += pdf[i];
        }
        double base[11];
        for (int i = 0; i < 11; ++i)
            base[i] = (double)((float)(pdf[i] / sum));

        double f[220];
        for (int i = 0; i < 220; ++i) f[i] = 0.0;
        for (int i = 0; i < 11; ++i) f[i] = base[i];
        int hw = 5;

        const double TAIL = 5e-4;
        for (int tt = 1; tt <= NT; ++tt) {
            double acc = 0.0;
            int r = 0;
            for (int a = hw; a >= 1; --a) {
                acc += f[hw + a];
                if (2.0 * acc > TAIL) { r = a; break; }
            }
            int ndp = (2 * r + 1 + 7) & ~7;          // pad taps to 8
            if (ndp > NDPMAX) ndp = NDPMAX;
            int rl = ndp / 2;                        // window: -rl .. ndp-1-rl
            P.rl[tt - 1] = rl;
            P.ndp[tt - 1] = ndp;
            for (int jj = 0; jj < ndp; ++jj) {
                int off = jj - rl;                   // true tail wts in padding
                float w = (off >= -hw && off <= hw) ? (float)f[hw + off] : 0.0f;
                float2 w2 = make_float2(w, w);
                memcpy(&P.K[tt - 1][jj], &w2, 8);
            }
            if (tt < NT) {   // f = f (*) base
                int L = 2 * hw + 1;
                double g[220];
                for (int i = 0; i < 220; ++i) g[i] = 0.0;
                for (int n = 0; n < L; ++n) {
                    double fn = f[n];
                    for (int k = 0; k < 11; ++k) g[n + k] += fn * base[k];
                }
                for (int i = 0; i < 220; ++i) f[i] = g[i];
                hw += 5;
            }
        }
        // Identity slot (t <= 0 safety): unit tap at offset 0 -> exact copy.
        P.rl[NT] = 4;
        P.ndp[NT] = 8;
        float2 one = make_float2(1.0f, 1.0f);
        memcpy(&P.K[NT][4], &one, 8);
    }

    dim3 block(256);
    dim3 grid(IMG / 16, CHAN, BATCH);   // 16 x 3 x 64 = 3072 CTAs
    blur_fused<<<grid, block>>>(x, out, t, P);
}